// round 2
// baseline (speedup 1.0000x reference)
#include <cuda_runtime.h>

// Problem constants: B=4, N=1024, C=256, H=8
#define Cc 256
#define Hh 8
#define KA 2048      // C*H, contraction length for W fold
#define KSPLIT 16    // split-K factor for kernel A (deterministic, no atomics)

// Scratch (no allocation allowed -> __device__ globals)
__device__ float g_partial[KSPLIT * Cc * Cc];  // 4 MB split-K partials
__device__ float g_W[Cc * Cc];                 // folded matrix W[j'][j]
__device__ float g_c[Cc];                      // folded bias vector

// ---------------------------------------------------------------------------
// Kernel A: partial_z[j'][j] = sum_{k in z-th chunk} Vr[k][j'] * lin[k][j]
//   k = i*H + h ; Vr[k][j'] = V[i*C*H + j'*H + h] ; lin row index == k.
//   Block: 64x64 output tile, 256 threads, 4x4 micro-tile per thread.
//   Grid: (4 j-tiles, 4 j'-tiles, 16 k-splits). Each split covers 16 i-values.
// ---------------------------------------------------------------------------
__global__ __launch_bounds__(256) void kA(const float* __restrict__ V,
                                          const float* __restrict__ lin) {
    __shared__ float As[8][68];   // [h][j'-local], pad 68 -> conflict-free stores
    __shared__ float Bs[8][64];   // [h][j-local]

    const int t  = threadIdx.x;
    const int tx = t & 15;        // j  micro coord
    const int ty = t >> 4;        // j' micro coord
    const int j0  = blockIdx.x * 64;
    const int jp0 = blockIdx.y * 64;
    const int z   = blockIdx.z;

    float acc[4][4] = {};

    for (int istep = 0; istep < 16; ++istep) {
        const int i = z * 16 + istep;

        // As: V[i, jp0:jp0+64, 0:8] is 512 CONTIGUOUS floats (j' stride 8, h stride 1)
        {
            const float* chunk = V + i * (Cc * Hh) + jp0 * Hh;
            float v0 = chunk[t];
            float v1 = chunk[t + 256];
            As[t & 7][t >> 3]         = v0;   // idx = j'*8 + h
            As[t & 7][(t + 256) >> 3] = v1;
        }
        // Bs: lin[i*8 + h][j0 + c], 8 rows of 64 contiguous floats
        {
            const float* bptr = lin + (i * Hh) * Cc + j0;
            int r = t >> 6;           // 0..3
            int c = t & 63;
            Bs[r][c]     = bptr[r * Cc + c];
            Bs[r + 4][c] = bptr[(r + 4) * Cc + c];
        }
        __syncthreads();

        #pragma unroll
        for (int h = 0; h < 8; ++h) {
            float a[4];
            #pragma unroll
            for (int e = 0; e < 4; ++e) a[e] = As[h][ty * 4 + e];
            float4 b4 = *(const float4*)&Bs[h][tx * 4];
            float b[4] = {b4.x, b4.y, b4.z, b4.w};
            #pragma unroll
            for (int e1 = 0; e1 < 4; ++e1)
                #pragma unroll
                for (int e2 = 0; e2 < 4; ++e2)
                    acc[e1][e2] = fmaf(a[e1], b[e2], acc[e1][e2]);
        }
        __syncthreads();
    }

    #pragma unroll
    for (int e1 = 0; e1 < 4; ++e1) {
        int jp = jp0 + ty * 4 + e1;
        float4 val = make_float4(acc[e1][0], acc[e1][1], acc[e1][2], acc[e1][3]);
        *(float4*)&g_partial[(z * Cc + jp) * Cc + j0 + tx * 4] = val;
    }
}

// ---------------------------------------------------------------------------
// Kernel R: reduce split-K partials into g_W; block 256 computes g_c.
// ---------------------------------------------------------------------------
__global__ __launch_bounds__(256) void kR(const float* __restrict__ lin,
                                          const float* __restrict__ biasV) {
    if (blockIdx.x < 256) {
        int idx = blockIdx.x * 256 + threadIdx.x;
        float s = 0.0f;
        #pragma unroll
        for (int z = 0; z < KSPLIT; ++z)
            s += g_partial[z * (Cc * Cc) + idx];
        g_W[idx] = s;
    } else {
        // c[j] = sum_k biasV[k] * lin[k*C + j]  (biasV flat index i*H+h == k)
        int j = threadIdx.x;
        float s0 = 0.f, s1 = 0.f, s2 = 0.f, s3 = 0.f;
        for (int k = 0; k < KA; k += 4) {
            s0 = fmaf(biasV[k + 0], lin[(k + 0) * Cc + j], s0);
            s1 = fmaf(biasV[k + 1], lin[(k + 1) * Cc + j], s1);
            s2 = fmaf(biasV[k + 2], lin[(k + 2) * Cc + j], s2);
            s3 = fmaf(biasV[k + 3], lin[(k + 3) * Cc + j], s3);
        }
        g_c[j] = (s0 + s1) + (s2 + s3);
    }
}

// ---------------------------------------------------------------------------
// Kernel B: out[m][j] = sum_{j'} v[m][j'] * W[j'][j] + c[j]
//   M = B*N = 4096, Nout = 256, K = 256.
//   Block: 64(m) x 64(j) tile, 256 threads, 4x4 micro. Grid (4, 64).
// ---------------------------------------------------------------------------
__global__ __launch_bounds__(256) void kB(const float* __restrict__ v,
                                          float* __restrict__ out) {
    __shared__ float Vs[64][17];  // [m-local][k-local], padded
    __shared__ float Ws[16][64];  // [k-local][j-local]

    const int t  = threadIdx.x;
    const int tx = t & 15;        // j micro coord
    const int ty = t >> 4;        // m micro coord
    const int j0 = blockIdx.x * 64;
    const int m0 = blockIdx.y * 64;

    float acc[4][4] = {};

    for (int ks = 0; ks < Cc; ks += 16) {
        // Vs: 64 rows x 16 cols, one float4 per thread
        {
            int r  = t >> 2;          // 0..63
            int c4 = (t & 3) * 4;     // 0,4,8,12
            float4 val = *(const float4*)&v[(m0 + r) * Cc + ks + c4];
            Vs[r][c4 + 0] = val.x; Vs[r][c4 + 1] = val.y;
            Vs[r][c4 + 2] = val.z; Vs[r][c4 + 3] = val.w;
        }
        // Ws: 16 rows x 64 cols, one float4 per thread
        {
            int r  = t >> 4;          // 0..15
            int c4 = (t & 15) * 4;
            *(float4*)&Ws[r][c4] = *(const float4*)&g_W[(ks + r) * Cc + j0 + c4];
        }
        __syncthreads();

        #pragma unroll
        for (int kk = 0; kk < 16; ++kk) {
            float a[4];
            #pragma unroll
            for (int e = 0; e < 4; ++e) a[e] = Vs[ty * 4 + e][kk];
            float4 b4 = *(const float4*)&Ws[kk][tx * 4];
            float b[4] = {b4.x, b4.y, b4.z, b4.w};
            #pragma unroll
            for (int e1 = 0; e1 < 4; ++e1)
                #pragma unroll
                for (int e2 = 0; e2 < 4; ++e2)
                    acc[e1][e2] = fmaf(a[e1], b[e2], acc[e1][e2]);
        }
        __syncthreads();
    }

    float4 cv = *(const float4*)&g_c[j0 + tx * 4];
    #pragma unroll
    for (int e1 = 0; e1 < 4; ++e1) {
        int m = m0 + ty * 4 + e1;
        float4 val = make_float4(acc[e1][0] + cv.x, acc[e1][1] + cv.y,
                                 acc[e1][2] + cv.z, acc[e1][3] + cv.w);
        *(float4*)&out[m * Cc + j0 + tx * 4] = val;
    }
}

// ---------------------------------------------------------------------------
// Inputs (metadata order): q, k, v, bias, atten_mask, Q, K, V,
//                          bias_Q, bias_K, bias_V, linear_output
// Only v (d_in[2]), V (d_in[7]), bias_V (d_in[10]), linear_output (d_in[11])
// matter: softmax over m sums to 1, so the attention block is the identity
// on vh; everything folds to out = v @ (Vr^T @ lin) + c.
// ---------------------------------------------------------------------------
extern "C" void kernel_launch(void* const* d_in, const int* in_sizes, int n_in,
                              void* d_out, int out_size) {
    const float* v     = (const float*)d_in[2];
    const float* V     = (const float*)d_in[7];
    const float* biasV = (const float*)d_in[10];
    const float* lin   = (const float*)d_in[11];
    float* out = (float*)d_out;

    kA<<<dim3(4, 4, KSPLIT), 256>>>(V, lin);
    kR<<<257, 256>>>(lin, biasV);
    kB<<<dim3(4, 64), 256>>>(v, out);
}

// round 3
// speedup vs baseline: 1.5308x; 1.5308x over previous
#include <cuda_runtime.h>

// Problem constants: B=4, N=1024, C=256, H=8
#define Cc 256
#define Hh 8
#define KA 2048      // C*H, contraction length for W fold
#define KSPLIT 32    // split-K factor for kernel A (deterministic, no atomics)

// Scratch (no allocation allowed -> __device__ globals)
__device__ float g_partial[KSPLIT * Cc * Cc];  // 8 MB split-K partials
__device__ float g_W[Cc * Cc];                 // folded matrix W[j'][j]
__device__ float g_c[Cc];                      // folded bias vector

// ---------------------------------------------------------------------------
// Kernel A: partial_z[j'][j] = sum_{k in z-th 64-chunk} Vr[k][j'] * lin[k][j]
//   k = i*H + h ; Vr[k][j'] = V[i*C*H + j'*H + h] ; lin row index == k.
//   Block: 64x64 output tile, 256 threads, 4x4 micro-tile.
//   Grid: (4 j-tiles, 4 j'-tiles, 32 k-splits); each split = 8 i's = 64 k.
//   ONE sync per block; compute phase is 1024 straight-line FMAs/thread.
// ---------------------------------------------------------------------------
__global__ __launch_bounds__(256) void kA(const float* __restrict__ V,
                                          const float* __restrict__ lin) {
    __shared__ float As[64][68];   // [k-local][j'-local]
    __shared__ float Bs[64][68];   // [k-local][j-local]

    const int t  = threadIdx.x;
    const int tx = t & 15;         // j  micro coord
    const int ty = t >> 4;         // j' micro coord
    const int j0  = blockIdx.x * 64;
    const int jp0 = blockIdx.y * 64;
    const int z   = blockIdx.z;

    // As: for each of 8 i's, V[i, jp0:jp0+64, 0:8] is 512 CONTIGUOUS floats
    // (j' stride 8, h stride 1). k-local = i_local*8 + h.
    #pragma unroll
    for (int il = 0; il < 8; ++il) {
        const float* chunk = V + (z * 8 + il) * (Cc * Hh) + jp0 * Hh;
        float v0 = chunk[t];
        float v1 = chunk[t + 256];
        As[il * 8 + (t & 7)][t >> 3]        = v0;
        As[il * 8 + (t & 7)][(t >> 3) + 32] = v1;
    }
    // Bs: lin rows z*64 .. z*64+63, cols j0..j0+63
    #pragma unroll
    for (int it = 0; it < 4; ++it) {
        int r  = (t >> 4) + it * 16;
        int c4 = (t & 15) * 4;
        *(float4*)&Bs[r][c4] = *(const float4*)&lin[(z * 64 + r) * Cc + j0 + c4];
    }
    __syncthreads();

    float acc[4][4] = {};
    #pragma unroll 16
    for (int k = 0; k < 64; ++k) {
        float4 a4 = *(const float4*)&As[k][ty * 4];
        float4 b4 = *(const float4*)&Bs[k][tx * 4];
        float a[4] = {a4.x, a4.y, a4.z, a4.w};
        float b[4] = {b4.x, b4.y, b4.z, b4.w};
        #pragma unroll
        for (int e1 = 0; e1 < 4; ++e1)
            #pragma unroll
            for (int e2 = 0; e2 < 4; ++e2)
                acc[e1][e2] = fmaf(a[e1], b[e2], acc[e1][e2]);
    }

    #pragma unroll
    for (int e1 = 0; e1 < 4; ++e1) {
        int jp = jp0 + ty * 4 + e1;
        float4 val = make_float4(acc[e1][0], acc[e1][1], acc[e1][2], acc[e1][3]);
        *(float4*)&g_partial[(z * Cc + jp) * Cc + j0 + tx * 4] = val;
    }
}

// ---------------------------------------------------------------------------
// Kernel R: reduce split-K partials into g_W; block 256 computes g_c.
// ---------------------------------------------------------------------------
__global__ __launch_bounds__(256) void kR(const float* __restrict__ lin,
                                          const float* __restrict__ biasV) {
    if (blockIdx.x < 256) {
        int idx = blockIdx.x * 256 + threadIdx.x;
        float s = 0.0f;
        #pragma unroll
        for (int z = 0; z < KSPLIT; ++z)
            s += g_partial[z * (Cc * Cc) + idx];
        g_W[idx] = s;
    } else {
        // c[j] = sum_k biasV[k] * lin[k*C + j]  (biasV flat index i*H+h == k)
        int j = threadIdx.x;
        float s0 = 0.f, s1 = 0.f, s2 = 0.f, s3 = 0.f;
        for (int k = 0; k < KA; k += 4) {
            s0 = fmaf(biasV[k + 0], lin[(k + 0) * Cc + j], s0);
            s1 = fmaf(biasV[k + 1], lin[(k + 1) * Cc + j], s1);
            s2 = fmaf(biasV[k + 2], lin[(k + 2) * Cc + j], s2);
            s3 = fmaf(biasV[k + 3], lin[(k + 3) * Cc + j], s3);
        }
        g_c[j] = (s0 + s1) + (s2 + s3);
    }
}

// ---------------------------------------------------------------------------
// Kernel B: out[m][j] = sum_{j'} v[m][j'] * W[j'][j] + c[j]
//   M = B*N = 4096, Nout = 256, K = 256.
//   Block: 64(m) x 64(j) tile, 256 threads, 4x4 micro. Grid (4, 64).
//   K staged in 64-wide chunks -> 8 syncs total (was 32), 1024-FMA phases.
// ---------------------------------------------------------------------------
__global__ __launch_bounds__(256) void kB(const float* __restrict__ v,
                                          float* __restrict__ out) {
    __shared__ float Vs[64][68];  // [m-local][k-local]
    __shared__ float Ws[64][68];  // [k-local][j-local]

    const int t  = threadIdx.x;
    const int tx = t & 15;        // j micro coord
    const int ty = t >> 4;        // m micro coord
    const int j0 = blockIdx.x * 64;
    const int m0 = blockIdx.y * 64;

    float acc[4][4] = {};

    for (int ks = 0; ks < Cc; ks += 64) {
        __syncthreads();  // previous chunk fully consumed
        #pragma unroll
        for (int it = 0; it < 4; ++it) {
            int r  = (t >> 4) + it * 16;   // m row
            int c4 = (t & 15) * 4;         // k col
            *(float4*)&Vs[r][c4] = *(const float4*)&v[(m0 + r) * Cc + ks + c4];
        }
        #pragma unroll
        for (int it = 0; it < 4; ++it) {
            int r  = (t >> 4) + it * 16;   // k row
            int c4 = (t & 15) * 4;         // j col
            *(float4*)&Ws[r][c4] = *(const float4*)&g_W[(ks + r) * Cc + j0 + c4];
        }
        __syncthreads();

        #pragma unroll 16
        for (int kk = 0; kk < 64; ++kk) {
            float a[4];
            #pragma unroll
            for (int e = 0; e < 4; ++e) a[e] = Vs[ty * 4 + e][kk];
            float4 b4 = *(const float4*)&Ws[kk][tx * 4];
            float b[4] = {b4.x, b4.y, b4.z, b4.w};
            #pragma unroll
            for (int e1 = 0; e1 < 4; ++e1)
                #pragma unroll
                for (int e2 = 0; e2 < 4; ++e2)
                    acc[e1][e2] = fmaf(a[e1], b[e2], acc[e1][e2]);
        }
    }

    float4 cv = *(const float4*)&g_c[j0 + tx * 4];
    #pragma unroll
    for (int e1 = 0; e1 < 4; ++e1) {
        int m = m0 + ty * 4 + e1;
        float4 val = make_float4(acc[e1][0] + cv.x, acc[e1][1] + cv.y,
                                 acc[e1][2] + cv.z, acc[e1][3] + cv.w);
        *(float4*)&out[m * Cc + j0 + tx * 4] = val;
    }
}

// ---------------------------------------------------------------------------
// Inputs (metadata order): q, k, v, bias, atten_mask, Q, K, V,
//                          bias_Q, bias_K, bias_V, linear_output
// Only v (d_in[2]), V (d_in[7]), bias_V (d_in[10]), linear_output (d_in[11])
// matter: softmax over m sums to 1, so the attention block is the identity
// on vh; everything folds to out = v @ (Vr^T @ lin) + c.
// ---------------------------------------------------------------------------
extern "C" void kernel_launch(void* const* d_in, const int* in_sizes, int n_in,
                              void* d_out, int out_size) {
    const float* v     = (const float*)d_in[2];
    const float* V     = (const float*)d_in[7];
    const float* biasV = (const float*)d_in[10];
    const float* lin   = (const float*)d_in[11];
    float* out = (float*)d_out;

    kA<<<dim3(4, 4, KSPLIT), 256>>>(V, lin);
    kR<<<257, 256>>>(lin, biasV);
    kB<<<dim3(4, 64), 256>>>(v, out);
}